// round 10
// baseline (speedup 1.0000x reference)
#include <cuda_runtime.h>
#include <cuda_fp16.h>
#include <cstdint>

#define SEQ 2048
#define DIM 128
#define BHN 32
#define NROWS (BHN * SEQ)   // 65536 rows each for q and k

// Normalized + sqrt(scale)-folded fp16 copies (16 MB each, device globals)
__device__ __half g_qh[(size_t)NROWS * DIM];
__device__ __half g_kh[(size_t)NROWS * DIM];

// ---------------------------------------------------------------------------
// Kernel 1: per-row normalize, fold sqrt(log2e/temp), convert to fp16.
// One warp per row.
// ---------------------------------------------------------------------------
__global__ void norm_cvt_kernel(const float* __restrict__ q,
                                const float* __restrict__ k,
                                const float* __restrict__ logt) {
    int gwarp = (blockIdx.x * blockDim.x + threadIdx.x) >> 5;
    int lane = threadIdx.x & 31;
    bool is_q = gwarp < NROWS;
    int row = is_q ? gwarp : gwarp - NROWS;
    const float* src = is_q ? q : k;
    float4 v = reinterpret_cast<const float4*>(src + (size_t)row * DIM)[lane];
    float ss = v.x * v.x + v.y * v.y + v.z * v.z + v.w * v.w;
#pragma unroll
    for (int o = 16; o > 0; o >>= 1) ss += __shfl_xor_sync(0xffffffffu, ss, o);

    const float LOG2E = 1.442695040888963f;
    float temp = fminf(fmaxf(__expf(*logt), 0.05f), 100.0f);
    float rsc = sqrtf(LOG2E / temp);
    float f = rsc / fmaxf(sqrtf(ss), 1e-12f);

    __half2 h0 = __floats2half2_rn(v.x * f, v.y * f);
    __half2 h1 = __floats2half2_rn(v.z * f, v.w * f);
    __half* dst = (is_q ? g_qh : g_kh) + (size_t)row * DIM + lane * 4;
    uint2 u;
    u.x = *reinterpret_cast<uint32_t*>(&h0);
    u.y = *reinterpret_cast<uint32_t*>(&h1);
    *reinterpret_cast<uint2*>(dst) = u;
}

// ---------------------------------------------------------------------------
// Helpers
// ---------------------------------------------------------------------------
__device__ __forceinline__ uint32_t smem_to_u32(const void* p) {
    uint32_t a;
    asm("{ .reg .u64 t; cvta.to.shared.u64 t, %1; cvt.u32.u64 %0, t; }" : "=r"(a) : "l"(p));
    return a;
}

// .cg: bypass L1 (L2 -> smem), data is consumed exactly once
#define CP_ASYNC16(dst, src) \
    asm volatile("cp.async.cg.shared.global [%0], [%1], 16;" :: "r"(dst), "l"(src))
#define CP_COMMIT() asm volatile("cp.async.commit_group;" ::: "memory")
#define CP_WAIT(n)  asm volatile("cp.async.wait_group %0;" :: "n"(n) : "memory")

__device__ __forceinline__ void ldsm_x4(unsigned r[4], uint32_t addr) {
    asm volatile("ldmatrix.sync.aligned.m8n8.x4.shared.b16 {%0,%1,%2,%3}, [%4];"
                 : "=r"(r[0]), "=r"(r[1]), "=r"(r[2]), "=r"(r[3]) : "r"(addr));
}

__device__ __forceinline__ void mma_f16(float c[4], const unsigned a[4],
                                        unsigned b0, unsigned b1) {
    asm volatile(
        "mma.sync.aligned.m16n8k16.row.col.f32.f16.f16.f32 "
        "{%0,%1,%2,%3}, {%4,%5,%6,%7}, {%8,%9}, {%0,%1,%2,%3};\n"
        : "+f"(c[0]), "+f"(c[1]), "+f"(c[2]), "+f"(c[3])
        : "r"(a[0]), "r"(a[1]), "r"(a[2]), "r"(a[3]), "r"(b0), "r"(b1));
}

__device__ __forceinline__ float ex2f(float x) {
    float y;
    asm("ex2.approx.f32 %0, %1;" : "=f"(y) : "f"(x));
    return y;
}

// ---------------------------------------------------------------------------
// Kernel 2: fp16 GEMM + exp epilogue. 2 CTAs/SM, 256 threads.
// CTA tile: M=128 x N=128, K=128 as 4 chunks of 32, 4 smem stages (no
// stage reuse): all chunk loads issued up-front, compute starts as soon as
// chunk 0 lands, progressive wait_group drain.
// Warp grid 2x4, warp tile 64x32 (acc 64 regs/lane).
// smem chunk row = 40 halves (80 B = 5 banks): 16 ldmatrix row pointers at
// stride 5 mod 32 hit 16 distinct banks -> conflict-free.
// Stage = A chunk + B chunk = 2*128*40*2 = 20480 B. Total 81920 B -> 2 CTAs.
// acc is in log2 domain (sqrt(scale) folded into both operands):
// epilogue = ex2(acc) + 1e-6.
// ---------------------------------------------------------------------------
#define LDH 40
#define HALF_CH (128 * LDH * 2)           // 10240  (one matrix chunk)
#define STAGE_BYTES (2 * HALF_CH)         // 20480
#define SMEM_TOTAL (4 * STAGE_BYTES)      // 81920

__global__ __launch_bounds__(256, 2) void hgemm_exp_kernel(float* __restrict__ out) {
    extern __shared__ char smem[];
    uint32_t sbase = smem_to_u32(smem);

    int bh = blockIdx.z;
    int bm = blockIdx.y;
    int bn = blockIdx.x;
    int tid = threadIdx.x;
    int warp = tid >> 5, lane = tid & 31;
    int wm = warp >> 2, wn = warp & 3;   // 2 x 4 warp grid
    int wmo = wm * 64, wno = wn * 32;    // warp tile 64 x 32

    const __half* qb = g_qh + ((size_t)bh * SEQ + (size_t)bm * 128) * DIM;
    const __half* kb = g_kh + ((size_t)bh * SEQ + (size_t)bn * 128) * DIM;

    // cp.async per chunk: A 512 + B 512 16B-transfers; 2 (A+B) pairs/thread/iter
    int ldr = tid >> 2;          // row 0..63 (then +64)
    int ldc4 = tid & 3;          // 8-half col group 0..3

    // ---- issue ALL 4 chunks up-front (one commit group each) ----
#pragma unroll
    for (int c = 0; c < 4; c++) {
        uint32_t st = sbase + (uint32_t)(c * STAGE_BYTES);
        const __half* qsrc = qb + c * 32 + ldc4 * 8;
        const __half* ksrc = kb + c * 32 + ldc4 * 8;
#pragma unroll
        for (int i = 0; i < 2; i++) {
            int r = ldr + i * 64;
            uint32_t o = (uint32_t)((r * LDH + ldc4 * 8) * 2);
            CP_ASYNC16(st + o, qsrc + (size_t)r * DIM);
            CP_ASYNC16(st + HALF_CH + o, ksrc + (size_t)r * DIM);
        }
        CP_COMMIT();
    }

    // ---- fragment offsets within a stage ----
    int l15 = lane & 15, lk = (lane >> 4) * 8;
    uint32_t aOff[4], bOff[2];
#pragma unroll
    for (int mi = 0; mi < 4; mi++)
        aOff[mi] = (uint32_t)(((wmo + mi * 16 + l15) * LDH + lk) * 2);
#pragma unroll
    for (int p = 0; p < 2; p++)
        bOff[p] = (uint32_t)(((wno + p * 16 + l15) * LDH + lk) * 2) + HALF_CH;

    float acc[4][4][4];
#pragma unroll
    for (int mi = 0; mi < 4; mi++)
#pragma unroll
        for (int ni = 0; ni < 4; ni++)
#pragma unroll
            for (int r = 0; r < 4; r++) acc[mi][ni][r] = 0.0f;

    // ---- 4 chunks x 2 ksteps of 16 ----
#pragma unroll
    for (int c = 0; c < 4; c++) {
        switch (c) {            // wait until chunk c's group has landed
            case 0: CP_WAIT(3); break;
            case 1: CP_WAIT(2); break;
            case 2: CP_WAIT(1); break;
            default: CP_WAIT(0); break;
        }
        __syncthreads();
        uint32_t st = sbase + (uint32_t)(c * STAGE_BYTES);

#pragma unroll
        for (int s = 0; s < 2; s++) {
            uint32_t kb32 = (uint32_t)(s * 32);   // 16 halves = 32 B
            unsigned af[4][4], bf[2][4];
#pragma unroll
            for (int mi = 0; mi < 4; mi++) ldsm_x4(af[mi], st + aOff[mi] + kb32);
#pragma unroll
            for (int p = 0; p < 2; p++) ldsm_x4(bf[p], st + bOff[p] + kb32);
            // mats {0,2} = n-rows 0-7 (k0-7, k8-15); mats {1,3} = n-rows 8-15
#pragma unroll
            for (int mi = 0; mi < 4; mi++)
#pragma unroll
                for (int p = 0; p < 2; p++) {
                    mma_f16(acc[mi][2 * p],     af[mi], bf[p][0], bf[p][2]);
                    mma_f16(acc[mi][2 * p + 1], af[mi], bf[p][1], bf[p][3]);
                }
        }
    }

    // ---- epilogue: out = ex2(acc) + 1e-6 ----
    int gid = lane >> 2, tig = lane & 3;
    int n0 = bn * 128;

#pragma unroll
    for (int mi = 0; mi < 4; mi++) {
        int r0 = wmo + mi * 16 + gid;
        float* o0p = out + ((size_t)bh * SEQ + (size_t)(bm * 128 + r0)) * SEQ + n0;
        float* o1p = o0p + (size_t)8 * SEQ;
#pragma unroll
        for (int ni = 0; ni < 4; ni++) {
            int c0 = wno + ni * 8 + tig * 2;
            float2 o0, o1;
            o0.x = ex2f(acc[mi][ni][0]) + 1e-6f;
            o0.y = ex2f(acc[mi][ni][1]) + 1e-6f;
            o1.x = ex2f(acc[mi][ni][2]) + 1e-6f;
            o1.y = ex2f(acc[mi][ni][3]) + 1e-6f;
            *reinterpret_cast<float2*>(o0p + c0) = o0;
            *reinterpret_cast<float2*>(o1p + c0) = o1;
        }
    }
}

// ---------------------------------------------------------------------------
// Launcher (graph-capturable: kernel launches only)
// ---------------------------------------------------------------------------
extern "C" void kernel_launch(void* const* d_in, const int* in_sizes, int n_in,
                              void* d_out, int out_size) {
    const float* q  = (const float*)d_in[0];
    const float* k  = (const float*)d_in[1];
    const float* lt = (const float*)d_in[2];
    float* out = (float*)d_out;

    norm_cvt_kernel<<<(2 * NROWS) / 8, 256>>>(q, k, lt);

    cudaFuncSetAttribute(hgemm_exp_kernel,
                         cudaFuncAttributeMaxDynamicSharedMemorySize, SMEM_TOTAL);
    dim3 grid(16, 16, 32);  // (bn, bm, bh)
    hgemm_exp_kernel<<<grid, 256, SMEM_TOTAL>>>(out);
}

// round 11
// speedup vs baseline: 1.1370x; 1.1370x over previous
#include <cuda_runtime.h>
#include <cuda_fp16.h>
#include <cstdint>

#define SEQ 2048
#define DIM 128
#define BHN 32
#define NROWS (BHN * SEQ)   // 65536 rows each for q and k

// Normalized + sqrt(scale)-folded fp16 copies (16 MB each, device globals)
__device__ __half g_qh[(size_t)NROWS * DIM];
__device__ __half g_kh[(size_t)NROWS * DIM];

// ---------------------------------------------------------------------------
// Kernel 1: per-row normalize, fold sqrt(log2e/temp), convert to fp16.
// One warp per row.
// ---------------------------------------------------------------------------
__global__ void norm_cvt_kernel(const float* __restrict__ q,
                                const float* __restrict__ k,
                                const float* __restrict__ logt) {
    int gwarp = (blockIdx.x * blockDim.x + threadIdx.x) >> 5;
    int lane = threadIdx.x & 31;
    bool is_q = gwarp < NROWS;
    int row = is_q ? gwarp : gwarp - NROWS;
    const float* src = is_q ? q : k;
    float4 v = reinterpret_cast<const float4*>(src + (size_t)row * DIM)[lane];
    float ss = v.x * v.x + v.y * v.y + v.z * v.z + v.w * v.w;
#pragma unroll
    for (int o = 16; o > 0; o >>= 1) ss += __shfl_xor_sync(0xffffffffu, ss, o);

    const float LOG2E = 1.442695040888963f;
    float temp = fminf(fmaxf(__expf(*logt), 0.05f), 100.0f);
    float rsc = sqrtf(LOG2E / temp);
    float f = rsc / fmaxf(sqrtf(ss), 1e-12f);

    __half2 h0 = __floats2half2_rn(v.x * f, v.y * f);
    __half2 h1 = __floats2half2_rn(v.z * f, v.w * f);
    __half* dst = (is_q ? g_qh : g_kh) + (size_t)row * DIM + lane * 4;
    uint2 u;
    u.x = *reinterpret_cast<uint32_t*>(&h0);
    u.y = *reinterpret_cast<uint32_t*>(&h1);
    *reinterpret_cast<uint2*>(dst) = u;
}

// ---------------------------------------------------------------------------
// Helpers
// ---------------------------------------------------------------------------
__device__ __forceinline__ uint32_t smem_to_u32(const void* p) {
    uint32_t a;
    asm("{ .reg .u64 t; cvta.to.shared.u64 t, %1; cvt.u32.u64 %0, t; }" : "=r"(a) : "l"(p));
    return a;
}

// .ca: keep fills in L1 — co-resident CTAs and neighbor-bn CTAs share tiles
#define CP_ASYNC16(dst, src) \
    asm volatile("cp.async.ca.shared.global [%0], [%1], 16;" :: "r"(dst), "l"(src))
#define CP_COMMIT() asm volatile("cp.async.commit_group;" ::: "memory")
#define CP_WAIT(n)  asm volatile("cp.async.wait_group %0;" :: "n"(n) : "memory")

__device__ __forceinline__ void ldsm_x4(unsigned r[4], uint32_t addr) {
    asm volatile("ldmatrix.sync.aligned.m8n8.x4.shared.b16 {%0,%1,%2,%3}, [%4];"
                 : "=r"(r[0]), "=r"(r[1]), "=r"(r[2]), "=r"(r[3]) : "r"(addr));
}

__device__ __forceinline__ void mma_f16(float c[4], const unsigned a[4],
                                        unsigned b0, unsigned b1) {
    asm volatile(
        "mma.sync.aligned.m16n8k16.row.col.f32.f16.f16.f32 "
        "{%0,%1,%2,%3}, {%4,%5,%6,%7}, {%8,%9}, {%0,%1,%2,%3};\n"
        : "+f"(c[0]), "+f"(c[1]), "+f"(c[2]), "+f"(c[3])
        : "r"(a[0]), "r"(a[1]), "r"(a[2]), "r"(a[3]), "r"(b0), "r"(b1));
}

__device__ __forceinline__ float ex2f(float x) {
    float y;
    asm("ex2.approx.f32 %0, %1;" : "=f"(y) : "f"(x));
    return y;
}

// streaming store: output is written once, never re-read -> evict-first in L2
__device__ __forceinline__ void stg_cs_v2(float* p, float x, float y) {
    asm volatile("st.global.cs.v2.f32 [%0], {%1, %2};" :: "l"(p), "f"(x), "f"(y) : "memory");
}

// ---------------------------------------------------------------------------
// Kernel 2: fp16 GEMM + exp epilogue. 2 CTAs/SM, 256 threads.
// CTA tile: M=128 x N=128, K=128 in two chunks of 64, 2 smem stages.
// Warp grid 2x4, warp tile 64x32 (acc 64 regs/lane).
// In-warp fragment software pipeline: k-step s+1's 6 LDSM issued before
// step s's 16 MMAs retire (hides LDS latency at 4 warps/SMSP).
// smem chunk row = 72 halves (144 B): conflict-free ldmatrix pointers.
// Stage = A chunk + B chunk = 36864 B. Total 73728 B -> 2 CTAs/SM.
// acc is in log2 domain (sqrt(scale) folded into both operands):
// epilogue = ex2(acc) + 1e-6.
// ---------------------------------------------------------------------------
#define LDH 72
#define CH_BYTES (128 * LDH * 2)          // 18432
#define STAGE_BYTES (2 * CH_BYTES)        // 36864
#define SMEM_TOTAL (2 * STAGE_BYTES)      // 73728

__global__ __launch_bounds__(256, 2) void hgemm_exp_kernel(float* __restrict__ out) {
    extern __shared__ char smem[];
    uint32_t sbase = smem_to_u32(smem);

    int bh = blockIdx.z;
    int bm = blockIdx.y;
    int bn = blockIdx.x;
    int tid = threadIdx.x;
    int warp = tid >> 5, lane = tid & 31;
    int wm = warp >> 2, wn = warp & 3;   // 2 x 4 warp grid
    int wmo = wm * 64, wno = wn * 32;    // warp tile 64 x 32

    const __half* qb = g_qh + ((size_t)bh * SEQ + (size_t)bm * 128) * DIM;
    const __half* kb = g_kh + ((size_t)bh * SEQ + (size_t)bn * 128) * DIM;

    // cp.async: chunk matrix = 128 rows x 64 halves = 1024 16B-chunks -> 4/thr
    int ldr = tid >> 3;          // base row 0..31
    int ldc8 = tid & 7;          // 8-half column group

    auto issue_chunk = [&](int c, int s) {
        uint32_t stA = sbase + (uint32_t)(s * STAGE_BYTES);
        uint32_t stB = stA + CH_BYTES;
        const __half* qsrc = qb + c * 64 + ldc8 * 8;
        const __half* ksrc = kb + c * 64 + ldc8 * 8;
#pragma unroll
        for (int i = 0; i < 4; i++) {
            int r = ldr + i * 32;
            uint32_t o = (uint32_t)((r * LDH + ldc8 * 8) * 2);
            CP_ASYNC16(stA + o, qsrc + (size_t)r * DIM);
            CP_ASYNC16(stB + o, ksrc + (size_t)r * DIM);
        }
        CP_COMMIT();
    };

    issue_chunk(0, 0);
    issue_chunk(1, 1);

    // fragment offsets within a stage (halves*2 = bytes)
    int l15 = lane & 15, lk = (lane >> 4) * 8;
    uint32_t aOff[4], bOff[2];
#pragma unroll
    for (int mi = 0; mi < 4; mi++)
        aOff[mi] = (uint32_t)(((wmo + mi * 16 + l15) * LDH + lk) * 2);
#pragma unroll
    for (int p = 0; p < 2; p++)
        bOff[p] = (uint32_t)(((wno + p * 16 + l15) * LDH + lk) * 2) + CH_BYTES;

    float acc[4][4][4];
#pragma unroll
    for (int mi = 0; mi < 4; mi++)
#pragma unroll
        for (int ni = 0; ni < 4; ni++)
#pragma unroll
            for (int r = 0; r < 4; r++) acc[mi][ni][r] = 0.0f;

    unsigned af[2][4][4], bf[2][2][4];

    // ---- 2 chunks x 4 ksteps of 16, fragments pipelined one step ahead ----
#pragma unroll
    for (int c = 0; c < 2; c++) {
        if (c == 0) { CP_WAIT(1); } else { CP_WAIT(0); }
        __syncthreads();
        uint32_t st = sbase + (uint32_t)(c * STAGE_BYTES);

        // prime step 0
#pragma unroll
        for (int mi = 0; mi < 4; mi++) ldsm_x4(af[0][mi], st + aOff[mi]);
#pragma unroll
        for (int p = 0; p < 2; p++) ldsm_x4(bf[0][p], st + bOff[p]);

#pragma unroll
        for (int s = 0; s < 4; s++) {
            int cur = s & 1, nxt = cur ^ 1;
            if (s < 3) {
                uint32_t kb32 = (uint32_t)((s + 1) * 32);
#pragma unroll
                for (int mi = 0; mi < 4; mi++) ldsm_x4(af[nxt][mi], st + aOff[mi] + kb32);
#pragma unroll
                for (int p = 0; p < 2; p++) ldsm_x4(bf[nxt][p], st + bOff[p] + kb32);
            }
            // mats {0,2} = n-rows 0-7 (k0-7, k8-15); mats {1,3} = n-rows 8-15
#pragma unroll
            for (int mi = 0; mi < 4; mi++)
#pragma unroll
                for (int p = 0; p < 2; p++) {
                    mma_f16(acc[mi][2 * p],     af[cur][mi], bf[cur][p][0], bf[cur][p][2]);
                    mma_f16(acc[mi][2 * p + 1], af[cur][mi], bf[cur][p][1], bf[cur][p][3]);
                }
        }
    }

    // ---- epilogue: out = ex2(acc) + 1e-6, streaming stores ----
    int gid = lane >> 2, tig = lane & 3;
    int n0 = bn * 128;

#pragma unroll
    for (int mi = 0; mi < 4; mi++) {
        int r0 = wmo + mi * 16 + gid;
        float* o0p = out + ((size_t)bh * SEQ + (size_t)(bm * 128 + r0)) * SEQ + n0;
        float* o1p = o0p + (size_t)8 * SEQ;
#pragma unroll
        for (int ni = 0; ni < 4; ni++) {
            int c0 = wno + ni * 8 + tig * 2;
            stg_cs_v2(o0p + c0, ex2f(acc[mi][ni][0]) + 1e-6f,
                                ex2f(acc[mi][ni][1]) + 1e-6f);
            stg_cs_v2(o1p + c0, ex2f(acc[mi][ni][2]) + 1e-6f,
                                ex2f(acc[mi][ni][3]) + 1e-6f);
        }
    }
}

// ---------------------------------------------------------------------------
// Launcher (graph-capturable: kernel launches only)
// ---------------------------------------------------------------------------
extern "C" void kernel_launch(void* const* d_in, const int* in_sizes, int n_in,
                              void* d_out, int out_size) {
    const float* q  = (const float*)d_in[0];
    const float* k  = (const float*)d_in[1];
    const float* lt = (const float*)d_in[2];
    float* out = (float*)d_out;

    norm_cvt_kernel<<<(2 * NROWS) / 8, 256>>>(q, k, lt);

    cudaFuncSetAttribute(hgemm_exp_kernel,
                         cudaFuncAttributeMaxDynamicSharedMemorySize, SMEM_TOTAL);
    dim3 grid(16, 16, 32);  // (bn, bm, bh)
    hgemm_exp_kernel<<<grid, 256, SMEM_TOTAL>>>(out);
}